// round 1
// baseline (speedup 1.0000x reference)
#include <cuda_runtime.h>
#include <math_constants.h>

// Problem: x[8,2048,1024] f32, codebook[8192,1024] f32.
// logits = x @ cb^T  -> argmax over codes -> gather codebook row.
// Output is an exact gather, so preserving argmax => rel_err == 0.

#define M_TOTAL 16384   // 8*2048 rows
#define N_CODES 8192
#define K_DIM   1024
#define NSPLIT  16      // code-range splits (512 codes each)
#define MTILE   128

// Scratch for per-(row, split) partial argmax. Static __device__ (no allocs).
__device__ float g_pmax[M_TOTAL * NSPLIT];
__device__ int   g_pidx[M_TOTAL * NSPLIT];

// ---------------------------------------------------------------------------
// Kernel 1: fused GEMM + running argmax over a 512-code split.
// Block = 256 threads (16x16), each thread owns an 8x8 micro-tile.
// Thread rows: m0 + ty*8 + i ; thread codes (per 128-code subtile): nb + tx*8 + j
// ---------------------------------------------------------------------------
__global__ __launch_bounds__(256, 2)
void partial_argmax_kernel(const float* __restrict__ x,
                           const float* __restrict__ cb) {
    const int m0  = blockIdx.y * MTILE;
    const int n0  = blockIdx.x * (N_CODES / NSPLIT);   // 512-code range
    const int tid = threadIdx.x;
    const int tx  = tid & 15;
    const int ty  = tid >> 4;

    __shared__ float As[8][128];   // [k][m]
    __shared__ float Bs[8][128];   // [k][n]
    __shared__ float smax[128][16];
    __shared__ int   sidx[128][16];

    float rmax[8];
    int   ridx[8];
#pragma unroll
    for (int i = 0; i < 8; ++i) { rmax[i] = -CUDART_INF_F; ridx[i] = 0; }

    // gmem tile-load mapping: one float4 per thread per operand per K-tile
    const int lrow = tid >> 1;          // 0..127
    const int lkq  = (tid & 1) << 2;    // 0 or 4
    const float* xg = x + (size_t)(m0 + lrow) * K_DIM + lkq;

    for (int ns = 0; ns < 4; ++ns) {    // 4 x 128-code subtiles
        const int nb = n0 + ns * 128;
        const float* cg = cb + (size_t)(nb + lrow) * K_DIM + lkq;

        float acc[8][8];
#pragma unroll
        for (int i = 0; i < 8; ++i)
#pragma unroll
            for (int j = 0; j < 8; ++j) acc[i][j] = 0.f;

        // register prefetch of tile 0
        float4 av = *(const float4*)xg;
        float4 bv = *(const float4*)cg;

        for (int kt = 0; kt < K_DIM / 8; ++kt) {
            __syncthreads();
            As[lkq + 0][lrow] = av.x; As[lkq + 1][lrow] = av.y;
            As[lkq + 2][lrow] = av.z; As[lkq + 3][lrow] = av.w;
            Bs[lkq + 0][lrow] = bv.x; Bs[lkq + 1][lrow] = bv.y;
            Bs[lkq + 2][lrow] = bv.z; Bs[lkq + 3][lrow] = bv.w;
            __syncthreads();
            if (kt + 1 < K_DIM / 8) {   // prefetch next tile while FFMAs run
                av = *(const float4*)(xg + (kt + 1) * 8);
                bv = *(const float4*)(cg + (kt + 1) * 8);
            }
#pragma unroll
            for (int k = 0; k < 8; ++k) {
                float a[8], b[8];
                *(float4*)&a[0] = *(const float4*)&As[k][ty * 8];
                *(float4*)&a[4] = *(const float4*)&As[k][ty * 8 + 4];
                *(float4*)&b[0] = *(const float4*)&Bs[k][tx * 8];
                *(float4*)&b[4] = *(const float4*)&Bs[k][tx * 8 + 4];
#pragma unroll
                for (int i = 0; i < 8; ++i)
#pragma unroll
                    for (int j = 0; j < 8; ++j)
                        acc[i][j] = fmaf(a[i], b[j], acc[i][j]);
            }
        }

        // fold this 128-code subtile into the running per-row argmax.
        // Codes ascend within a thread (ns asc, j asc) so strict '>' keeps
        // the lowest index on exact ties (matches jnp.argmax first-hit).
#pragma unroll
        for (int i = 0; i < 8; ++i)
#pragma unroll
            for (int j = 0; j < 8; ++j) {
                const int code = nb + tx * 8 + j;
                if (acc[i][j] > rmax[i]) { rmax[i] = acc[i][j]; ridx[i] = code; }
            }
    }

    // cross-thread (tx) reduction per row
#pragma unroll
    for (int i = 0; i < 8; ++i) {
        smax[ty * 8 + i][tx] = rmax[i];
        sidx[ty * 8 + i][tx] = ridx[i];
    }
    __syncthreads();
    if (tid < 128) {
        float best = smax[tid][0]; int bi = sidx[tid][0];
#pragma unroll
        for (int t = 1; t < 16; ++t) {
            const float v = smax[tid][t]; const int id = sidx[tid][t];
            if (v > best || (v == best && id < bi)) { best = v; bi = id; }
        }
        g_pmax[(size_t)(m0 + tid) * NSPLIT + blockIdx.x] = best;
        g_pidx[(size_t)(m0 + tid) * NSPLIT + blockIdx.x] = bi;
    }
}

// ---------------------------------------------------------------------------
// Kernel 2: reduce the 16 split-partials per row, gather the codebook row.
// ---------------------------------------------------------------------------
__global__ void finalize_kernel(const float* __restrict__ cb,
                                float* __restrict__ out) {
    const int row = blockIdx.x;
    __shared__ int s_bi;
    if (threadIdx.x == 0) {
        const float* pm = &g_pmax[(size_t)row * NSPLIT];
        const int*   pi = &g_pidx[(size_t)row * NSPLIT];
        float best = pm[0]; int bi = pi[0];
#pragma unroll
        for (int s = 1; s < NSPLIT; ++s) {
            const float v = pm[s]; const int id = pi[s];
            if (v > best || (v == best && id < bi)) { best = v; bi = id; }
        }
        s_bi = bi;
    }
    __syncthreads();
    const float4* src = (const float4*)(cb + (size_t)s_bi * K_DIM);
    float4*       dst = (float4*)(out + (size_t)row * K_DIM);
#pragma unroll
    for (int i = threadIdx.x; i < K_DIM / 4; i += 128) dst[i] = src[i];
}

extern "C" void kernel_launch(void* const* d_in, const int* in_sizes, int n_in,
                              void* d_out, int out_size) {
    const float* x  = (const float*)d_in[0];   // [8,2048,1024]
    const float* cb = (const float*)d_in[1];   // [8192,1024]
    float* out = (float*)d_out;                // [8,2048,1024]

    dim3 grid(NSPLIT, M_TOTAL / MTILE);        // (16, 128) = 2048 CTAs
    partial_argmax_kernel<<<grid, 256>>>(x, cb);
    finalize_kernel<<<M_TOTAL, 128>>>(cb, out);
}

// round 6
// speedup vs baseline: 6.8186x; 6.8186x over previous
#include <cuda_runtime.h>
#include <cuda_fp16.h>
#include <cstdint>
#include <math_constants.h>

// logits = x[16384,1024] @ cb[8192,1024]^T ; argmax over codes ; gather cb row.
// Phase 0: convert x, cb to fp16 (static buffers).
// Phase 1: fp16 mma.sync GEMM -> fp16 logits (static 256MB buffer).
// Phase 2: per-row max + candidate set (margin) + exact fp32 rescore + gather.

#define M_TOTAL 16384
#define N_CODES 8192
#define K_DIM   1024

#define BM 128
#define BN 256
#define BK 64
#define STAGES 3
#define KT_ITERS (K_DIM / BK)   // 16

#define MARGIN 1.0f
#define CAND_CAP 64

// ---- static device buffers (no allocations allowed) ----
__device__ uint4  g_xh4[(size_t)M_TOTAL * K_DIM / 8];    // fp16 x   (32 MB)
__device__ uint4  g_cbh4[(size_t)N_CODES * K_DIM / 8];   // fp16 cb  (16 MB)
__device__ __half g_logits[(size_t)M_TOTAL * N_CODES];   // fp16 logits (256 MB)

#define SWZ(b) ((b) ^ (((b) >> 3) & 0x70))

__device__ __forceinline__ uint32_t s2u(const void* p) {
    return (uint32_t)__cvta_generic_to_shared(p);
}
__device__ __forceinline__ void cpasync16(uint32_t dst, const void* src) {
    asm volatile("cp.async.cg.shared.global [%0], [%1], 16;" :: "r"(dst), "l"(src));
}
__device__ __forceinline__ void ldsm4(uint32_t& r0, uint32_t& r1, uint32_t& r2,
                                      uint32_t& r3, uint32_t addr) {
    asm volatile("ldmatrix.sync.aligned.m8n8.x4.shared.b16 {%0,%1,%2,%3}, [%4];"
                 : "=r"(r0), "=r"(r1), "=r"(r2), "=r"(r3) : "r"(addr));
}
__device__ __forceinline__ void mma16816(float* c, const uint32_t* a, const uint32_t* b) {
    asm volatile(
        "mma.sync.aligned.m16n8k16.row.col.f32.f16.f16.f32 "
        "{%0,%1,%2,%3}, {%4,%5,%6,%7}, {%8,%9}, {%0,%1,%2,%3};"
        : "+f"(c[0]), "+f"(c[1]), "+f"(c[2]), "+f"(c[3])
        : "r"(a[0]), "r"(a[1]), "r"(a[2]), "r"(a[3]), "r"(b[0]), "r"(b[1]));
}

// ---------------------------------------------------------------------------
// Phase 0: f32 -> f16 conversion (8 floats -> one uint4 of 8 halves)
// ---------------------------------------------------------------------------
__global__ void cvt_x_kernel(const float* __restrict__ src) {
    int i = blockIdx.x * blockDim.x + threadIdx.x;
    if (i >= (int)(M_TOTAL * K_DIM / 8)) return;
    const float4* s = (const float4*)src;
    float4 a = s[2 * i], b = s[2 * i + 1];
    __half2 h0 = __floats2half2_rn(a.x, a.y), h1 = __floats2half2_rn(a.z, a.w);
    __half2 h2 = __floats2half2_rn(b.x, b.y), h3 = __floats2half2_rn(b.z, b.w);
    uint4 o;
    o.x = *(uint32_t*)&h0; o.y = *(uint32_t*)&h1;
    o.z = *(uint32_t*)&h2; o.w = *(uint32_t*)&h3;
    g_xh4[i] = o;
}
__global__ void cvt_cb_kernel(const float* __restrict__ src) {
    int i = blockIdx.x * blockDim.x + threadIdx.x;
    if (i >= (int)(N_CODES * K_DIM / 8)) return;
    const float4* s = (const float4*)src;
    float4 a = s[2 * i], b = s[2 * i + 1];
    __half2 h0 = __floats2half2_rn(a.x, a.y), h1 = __floats2half2_rn(a.z, a.w);
    __half2 h2 = __floats2half2_rn(b.x, b.y), h3 = __floats2half2_rn(b.z, b.w);
    uint4 o;
    o.x = *(uint32_t*)&h0; o.y = *(uint32_t*)&h1;
    o.z = *(uint32_t*)&h2; o.w = *(uint32_t*)&h3;
    g_cbh4[i] = o;
}

// ---------------------------------------------------------------------------
// Phase 1: fp16 GEMM, 128x256 tile, BK=64, 3-stage cp.async, 16 warps (4m x 4n)
// warp tile 32(m) x 64(n): 2x8 grid of m16n8k16.
// ---------------------------------------------------------------------------
__global__ __launch_bounds__(512, 1)
void gemm_f16_kernel() {
    extern __shared__ char smem[];
    const int tid = threadIdx.x;
    const int wid = tid >> 5, lane = tid & 31;
    const int wm = wid >> 2, wn = wid & 3;
    const int m0 = blockIdx.y * BM, n0 = blockIdx.x * BN;
    const __half* xh  = (const __half*)g_xh4;
    const __half* cbh = (const __half*)g_cbh4;

    char* sA = smem;                         // STAGES * 128*128B = 48KB
    char* sB = smem + STAGES * BM * 128;     // STAGES * 256*128B = 96KB

    float acc[2][8][4];
#pragma unroll
    for (int mi = 0; mi < 2; ++mi)
#pragma unroll
        for (int ni = 0; ni < 8; ++ni)
#pragma unroll
            for (int j = 0; j < 4; ++j) acc[mi][ni][j] = 0.f;

    auto load_stage = [&](int s, int kt) {
#pragma unroll
        for (int q = 0; q < 2; ++q) {           // A: 1024 16B chunks
            int f = tid + 512 * q;
            int row = f >> 3, kc = f & 7;
            uint32_t d = s2u(sA + s * BM * 128 + SWZ(row * 128 + kc * 16));
            cpasync16(d, xh + (size_t)(m0 + row) * K_DIM + kt * BK + kc * 8);
        }
#pragma unroll
        for (int q = 0; q < 4; ++q) {           // B: 2048 16B chunks
            int f = tid + 512 * q;
            int row = f >> 3, kc = f & 7;
            uint32_t d = s2u(sB + s * BN * 128 + SWZ(row * 128 + kc * 16));
            cpasync16(d, cbh + (size_t)(n0 + row) * K_DIM + kt * BK + kc * 8);
        }
    };

    for (int s = 0; s < STAGES - 1; ++s) {
        load_stage(s, s);
        asm volatile("cp.async.commit_group;");
    }

    for (int kt = 0; kt < KT_ITERS; ++kt) {
        __syncthreads();   // compute of (kt-1) done before its buffer is reloaded
        int ls = kt + STAGES - 1;
        if (ls < KT_ITERS) load_stage(ls % STAGES, ls);
        asm volatile("cp.async.commit_group;");
        asm volatile("cp.async.wait_group 2;");
        __syncthreads();   // stage kt visible to all threads

        char* bA = sA + (kt % STAGES) * BM * 128;
        char* bB = sB + (kt % STAGES) * BN * 128;
#pragma unroll
        for (int ks = 0; ks < 4; ++ks) {        // 4 x k16 per stage
            uint32_t afr[2][4];
#pragma unroll
            for (int mi = 0; mi < 2; ++mi) {
                int row = wm * 32 + mi * 16 + (lane & 15);
                int col = ks * 32 + ((lane >> 4) << 4);
                ldsm4(afr[mi][0], afr[mi][1], afr[mi][2], afr[mi][3],
                      s2u(bA + SWZ(row * 128 + col)));
            }
            uint32_t bfr[8][2];
#pragma unroll
            for (int pi = 0; pi < 4; ++pi) {    // each x4 covers two n8 tiles
                int row = wn * 64 + pi * 16 + ((lane >> 4) << 3) + (lane & 7);
                int col = ks * 32 + ((lane >> 3) & 1) * 16;
                uint32_t r0, r1, r2, r3;
                ldsm4(r0, r1, r2, r3, s2u(bB + SWZ(row * 128 + col)));
                bfr[2 * pi][0] = r0; bfr[2 * pi][1] = r1;
                bfr[2 * pi + 1][0] = r2; bfr[2 * pi + 1][1] = r3;
            }
#pragma unroll
            for (int mi = 0; mi < 2; ++mi)
#pragma unroll
                for (int ni = 0; ni < 8; ++ni)
                    mma16816(acc[mi][ni], afr[mi], bfr[ni]);
        }
    }

    // epilogue: fp16 logits.  d-frag: rows lane/4 and lane/4+8, cols (lane%4)*2.
#pragma unroll
    for (int mi = 0; mi < 2; ++mi)
#pragma unroll
        for (int ni = 0; ni < 8; ++ni) {
            int m = m0 + wm * 32 + mi * 16 + (lane >> 2);
            int n = n0 + wn * 64 + ni * 8 + (lane & 3) * 2;
            __half2 h0 = __floats2half2_rn(acc[mi][ni][0], acc[mi][ni][1]);
            __half2 h1 = __floats2half2_rn(acc[mi][ni][2], acc[mi][ni][3]);
            *(__half2*)(g_logits + (size_t)m * N_CODES + n) = h0;
            *(__half2*)(g_logits + (size_t)(m + 8) * N_CODES + n) = h1;
        }
}

// ---------------------------------------------------------------------------
// Phase 2: per-row screening max + candidates, fp32 rescore, gather. 1 block/row.
// ---------------------------------------------------------------------------
__global__ __launch_bounds__(256)
void argmax_gather_kernel(const float* __restrict__ x,
                          const float* __restrict__ cb,
                          float* __restrict__ out) {
    const int row = blockIdx.x;
    const int tid = threadIdx.x;
    const __half2* lg = (const __half2*)(g_logits + (size_t)row * N_CODES);

    __shared__ float s_red[8];
    __shared__ float s_bcast;
    __shared__ int   s_cand[CAND_CAP];
    __shared__ int   s_cnt;

    // pass 1: row max
    float mx = -CUDART_INF_F;
    for (int i = tid; i < N_CODES / 2; i += 256) {
        float2 v = __half22float2(lg[i]);
        mx = fmaxf(mx, fmaxf(v.x, v.y));
    }
#pragma unroll
    for (int o = 16; o; o >>= 1) mx = fmaxf(mx, __shfl_xor_sync(~0u, mx, o));
    if ((tid & 31) == 0) s_red[tid >> 5] = mx;
    if (tid == 0) s_cnt = 0;
    __syncthreads();
    if (tid == 0) {
        float m = s_red[0];
#pragma unroll
        for (int j = 1; j < 8; ++j) m = fmaxf(m, s_red[j]);
        s_bcast = m;
    }
    __syncthreads();
    const float thr = s_bcast - MARGIN;

    // pass 2: candidates within margin
    for (int i = tid; i < N_CODES / 2; i += 256) {
        float2 v = __half22float2(lg[i]);
        if (v.x > thr) { int p = atomicAdd(&s_cnt, 1); if (p < CAND_CAP) s_cand[p] = 2 * i; }
        if (v.y > thr) { int p = atomicAdd(&s_cnt, 1); if (p < CAND_CAP) s_cand[p] = 2 * i + 1; }
    }
    __syncthreads();
    const int ncand = s_cnt;

    int best;
    if (ncand == 1) {
        best = s_cand[0];
    } else {
        const bool full = (ncand > CAND_CAP);     // astronomically unlikely
        const int ntot = full ? N_CODES : ncand;
        float bv = -CUDART_INF_F;
        best = N_CODES;
        const float4* xr = (const float4*)(x + (size_t)row * K_DIM);
        const float4 a = xr[tid];                 // 256 thr x float4 = K=1024
        for (int ci = 0; ci < ntot; ++ci) {
            const int code = full ? ci : s_cand[ci];
            const float4* cr = (const float4*)(cb + (size_t)code * K_DIM);
            const float4 b = cr[tid];
            float p = a.x * b.x + a.y * b.y + a.z * b.z + a.w * b.w;
#pragma unroll
            for (int o = 16; o; o >>= 1) p += __shfl_xor_sync(~0u, p, o);
            if ((tid & 31) == 0) s_red[tid >> 5] = p;
            __syncthreads();
            if (tid == 0) {
                float s = 0.f;
#pragma unroll
                for (int j = 0; j < 8; ++j) s += s_red[j];
                s_bcast = s;
            }
            __syncthreads();
            const float dot = s_bcast;
            if (dot > bv || (dot == bv && code < best)) { bv = dot; best = code; }
            __syncthreads();
        }
    }

    // gather winning codebook row (1024 floats, one float4 per thread)
    const float4* src = (const float4*)(cb + (size_t)best * K_DIM);
    float4* dst = (float4*)(out + (size_t)row * K_DIM);
    dst[tid] = src[tid];
}

// ---------------------------------------------------------------------------
extern "C" void kernel_launch(void* const* d_in, const int* in_sizes, int n_in,
                              void* d_out, int out_size) {
    const float* x  = (const float*)d_in[0];   // [8,2048,1024]
    const float* cb = (const float*)d_in[1];   // [8192,1024]
    float* out = (float*)d_out;

    const int smem = STAGES * (BM + BN) * 128; // 147456
    cudaFuncSetAttribute(gemm_f16_kernel,
                         cudaFuncAttributeMaxDynamicSharedMemorySize, smem);

    cvt_x_kernel<<<(M_TOTAL * K_DIM / 8 + 255) / 256, 256>>>(x);
    cvt_cb_kernel<<<(N_CODES * K_DIM / 8 + 255) / 256, 256>>>(cb);

    dim3 grid(N_CODES / BN, M_TOTAL / BM);     // (32, 128)
    gemm_f16_kernel<<<grid, 512, smem>>>();

    argmax_gather_kernel<<<M_TOTAL, 256>>>(x, cb, out);
}

// round 7
// speedup vs baseline: 7.7097x; 1.1307x over previous
#include <cuda_runtime.h>
#include <cuda_fp16.h>
#include <cstdint>
#include <math_constants.h>

// logits = x[16384,1024] @ cb[8192,1024]^T ; argmax over codes ; gather cb row.
// Phase 0: convert x, cb to fp16.
// Phase 1: fp16 mma.sync GEMM; fused epilogue emits per-(row, n-tile) candidate
//          codes within MARGIN of the tile row-max (fp32 screening values).
// Phase 2: per-row global max over ~32 candidates, exact fp32 rescore if >1
//          candidate survives, gather codebook row.

#define M_TOTAL 16384
#define N_CODES 8192
#define K_DIM   1024

#define BM 128
#define BN 256
#define BK 64
#define STAGES 3
#define KT_ITERS (K_DIM / BK)   // 16
#define NTILE (N_CODES / BN)    // 32

#define MARGIN 0.35f
#define CAP 6          // candidate slots per (row, tile)
#define RCAP 64        // rescore list cap per row

// ---- static device buffers ----
__device__ uint4 g_xh4[(size_t)M_TOTAL * K_DIM / 8];    // fp16 x   (32 MB)
__device__ uint4 g_cbh4[(size_t)N_CODES * K_DIM / 8];   // fp16 cb  (16 MB)
__device__ int   g_ccnt[(size_t)M_TOTAL * NTILE];       // counts   (2 MB)
__device__ uint2 g_cand[(size_t)M_TOTAL * NTILE * CAP]; // {val,idx} (25 MB)

#define SWZ(b) ((b) ^ (((b) >> 3) & 0x70))

__device__ __forceinline__ uint32_t s2u(const void* p) {
    return (uint32_t)__cvta_generic_to_shared(p);
}
__device__ __forceinline__ void cpasync16(uint32_t dst, const void* src) {
    asm volatile("cp.async.cg.shared.global [%0], [%1], 16;" :: "r"(dst), "l"(src));
}
__device__ __forceinline__ void ldsm4(uint32_t& r0, uint32_t& r1, uint32_t& r2,
                                      uint32_t& r3, uint32_t addr) {
    asm volatile("ldmatrix.sync.aligned.m8n8.x4.shared.b16 {%0,%1,%2,%3}, [%4];"
                 : "=r"(r0), "=r"(r1), "=r"(r2), "=r"(r3) : "r"(addr));
}
__device__ __forceinline__ void mma16816(float* c, const uint32_t* a, const uint32_t* b) {
    asm volatile(
        "mma.sync.aligned.m16n8k16.row.col.f32.f16.f16.f32 "
        "{%0,%1,%2,%3}, {%4,%5,%6,%7}, {%8,%9}, {%0,%1,%2,%3};"
        : "+f"(c[0]), "+f"(c[1]), "+f"(c[2]), "+f"(c[3])
        : "r"(a[0]), "r"(a[1]), "r"(a[2]), "r"(a[3]), "r"(b[0]), "r"(b[1]));
}

// ---------------------------------------------------------------------------
// Phase 0: f32 -> f16
// ---------------------------------------------------------------------------
__global__ void cvt_x_kernel(const float* __restrict__ src) {
    int i = blockIdx.x * blockDim.x + threadIdx.x;
    if (i >= (int)(M_TOTAL * K_DIM / 8)) return;
    const float4* s = (const float4*)src;
    float4 a = s[2 * i], b = s[2 * i + 1];
    __half2 h0 = __floats2half2_rn(a.x, a.y), h1 = __floats2half2_rn(a.z, a.w);
    __half2 h2 = __floats2half2_rn(b.x, b.y), h3 = __floats2half2_rn(b.z, b.w);
    uint4 o;
    o.x = *(uint32_t*)&h0; o.y = *(uint32_t*)&h1;
    o.z = *(uint32_t*)&h2; o.w = *(uint32_t*)&h3;
    g_xh4[i] = o;
}
__global__ void cvt_cb_kernel(const float* __restrict__ src) {
    int i = blockIdx.x * blockDim.x + threadIdx.x;
    if (i >= (int)(N_CODES * K_DIM / 8)) return;
    const float4* s = (const float4*)src;
    float4 a = s[2 * i], b = s[2 * i + 1];
    __half2 h0 = __floats2half2_rn(a.x, a.y), h1 = __floats2half2_rn(a.z, a.w);
    __half2 h2 = __floats2half2_rn(b.x, b.y), h3 = __floats2half2_rn(b.z, b.w);
    uint4 o;
    o.x = *(uint32_t*)&h0; o.y = *(uint32_t*)&h1;
    o.z = *(uint32_t*)&h2; o.w = *(uint32_t*)&h3;
    g_cbh4[i] = o;
}

// ---------------------------------------------------------------------------
// Phase 1: fp16 GEMM 128x256, BK=64, 3-stage cp.async, 16 warps (4m x 4n),
// fused per-row tile-max + candidate emission epilogue.
// ---------------------------------------------------------------------------
__global__ __launch_bounds__(512, 1)
void gemm_f16_kernel() {
    extern __shared__ char smem[];
    const int tid = threadIdx.x;
    const int wid = tid >> 5, lane = tid & 31;
    const int wm = wid >> 2, wn = wid & 3;
    const int m0 = blockIdx.y * BM, n0 = blockIdx.x * BN;
    const __half* xh  = (const __half*)g_xh4;
    const __half* cbh = (const __half*)g_cbh4;

    char* sA = smem;                         // STAGES * 128*128B
    char* sB = smem + STAGES * BM * 128;     // STAGES * 256*128B

    float acc[2][8][4];
#pragma unroll
    for (int mi = 0; mi < 2; ++mi)
#pragma unroll
        for (int ni = 0; ni < 8; ++ni)
#pragma unroll
            for (int j = 0; j < 4; ++j) acc[mi][ni][j] = 0.f;

    auto load_stage = [&](int s, int kt) {
#pragma unroll
        for (int q = 0; q < 2; ++q) {
            int f = tid + 512 * q;
            int row = f >> 3, kc = f & 7;
            uint32_t d = s2u(sA + s * BM * 128 + SWZ(row * 128 + kc * 16));
            cpasync16(d, xh + (size_t)(m0 + row) * K_DIM + kt * BK + kc * 8);
        }
#pragma unroll
        for (int q = 0; q < 4; ++q) {
            int f = tid + 512 * q;
            int row = f >> 3, kc = f & 7;
            uint32_t d = s2u(sB + s * BN * 128 + SWZ(row * 128 + kc * 16));
            cpasync16(d, cbh + (size_t)(n0 + row) * K_DIM + kt * BK + kc * 8);
        }
    };

    for (int s = 0; s < STAGES - 1; ++s) {
        load_stage(s, s);
        asm volatile("cp.async.commit_group;");
    }

    for (int kt = 0; kt < KT_ITERS; ++kt) {
        __syncthreads();
        int ls = kt + STAGES - 1;
        if (ls < KT_ITERS) load_stage(ls % STAGES, ls);
        asm volatile("cp.async.commit_group;");
        asm volatile("cp.async.wait_group 2;");
        __syncthreads();

        char* bA = sA + (kt % STAGES) * BM * 128;
        char* bB = sB + (kt % STAGES) * BN * 128;
#pragma unroll
        for (int ks = 0; ks < 4; ++ks) {
            uint32_t afr[2][4];
#pragma unroll
            for (int mi = 0; mi < 2; ++mi) {
                int row = wm * 32 + mi * 16 + (lane & 15);
                int col = ks * 32 + ((lane >> 4) << 4);
                ldsm4(afr[mi][0], afr[mi][1], afr[mi][2], afr[mi][3],
                      s2u(bA + SWZ(row * 128 + col)));
            }
            uint32_t bfr[8][2];
#pragma unroll
            for (int pi = 0; pi < 4; ++pi) {
                int row = wn * 64 + pi * 16 + ((lane >> 4) << 3) + (lane & 7);
                int col = ks * 32 + ((lane >> 3) & 1) * 16;
                uint32_t r0, r1, r2, r3;
                ldsm4(r0, r1, r2, r3, s2u(bB + SWZ(row * 128 + col)));
                bfr[2 * pi][0] = r0; bfr[2 * pi][1] = r1;
                bfr[2 * pi + 1][0] = r2; bfr[2 * pi + 1][1] = r3;
            }
#pragma unroll
            for (int mi = 0; mi < 2; ++mi)
#pragma unroll
                for (int ni = 0; ni < 8; ++ni)
                    mma16816(acc[mi][ni], afr[mi], bfr[ni]);
        }
    }
    __syncthreads();   // all smem tile reads done; reuse smem for epilogue

    // ---- fused epilogue: per-row tile max + candidate emission ----
    // fragment: rows r = wm*32 + mi*16 + half*8 + (lane>>2);
    //           cols c = wn*64 + ni*8 + (lane&3)*2 + (j&1);  j = half*2 + (j&1)
    float* s_wmax = (float*)smem;                 // [128 rows][4 wn]
    float* s_rmax = (float*)(smem + 2048);        // [128]
    int*   s_cnt  = (int*)(smem + 2560);          // [128]
    uint2* s_slot = (uint2*)(smem + 3072);        // [128][CAP]

#pragma unroll
    for (int mi = 0; mi < 2; ++mi)
#pragma unroll
        for (int half = 0; half < 2; ++half) {
            float lm = -CUDART_INF_F;
#pragma unroll
            for (int ni = 0; ni < 8; ++ni)
                lm = fmaxf(lm, fmaxf(acc[mi][ni][half * 2], acc[mi][ni][half * 2 + 1]));
            lm = fmaxf(lm, __shfl_xor_sync(~0u, lm, 1));
            lm = fmaxf(lm, __shfl_xor_sync(~0u, lm, 2));
            if ((lane & 3) == 0) {
                int r = wm * 32 + mi * 16 + half * 8 + (lane >> 2);
                s_wmax[r * 4 + wn] = lm;
            }
        }
    if (tid < 128) s_cnt[tid] = 0;
    __syncthreads();
    if (tid < 128) {
        float m = fmaxf(fmaxf(s_wmax[tid * 4], s_wmax[tid * 4 + 1]),
                        fmaxf(s_wmax[tid * 4 + 2], s_wmax[tid * 4 + 3]));
        s_rmax[tid] = m;
    }
    __syncthreads();

#pragma unroll
    for (int mi = 0; mi < 2; ++mi)
#pragma unroll
        for (int half = 0; half < 2; ++half) {
            const int r = wm * 32 + mi * 16 + half * 8 + (lane >> 2);
            const float thr = s_rmax[r] - MARGIN;
#pragma unroll
            for (int ni = 0; ni < 8; ++ni)
#pragma unroll
                for (int jj = 0; jj < 2; ++jj) {
                    float v = acc[mi][ni][half * 2 + jj];
                    if (v > thr) {
                        int p = atomicAdd(&s_cnt[r], 1);
                        if (p < CAP) {
                            uint2 e;
                            e.x = __float_as_uint(v);
                            e.y = (uint32_t)(n0 + wn * 64 + ni * 8 + (lane & 3) * 2 + jj);
                            s_slot[r * CAP + p] = e;
                        }
                    }
                }
        }
    __syncthreads();
    if (tid < 128) {
        const int c = s_cnt[tid];
        const size_t base = ((size_t)(m0 + tid) * NTILE + blockIdx.x);
        g_ccnt[base] = c;
        const int cw = c < CAP ? c : CAP;
        for (int p = 0; p < cw; ++p)
            g_cand[base * CAP + p] = s_slot[tid * CAP + p];
    }
}

// ---------------------------------------------------------------------------
// Phase 2: global max over candidates, exact fp32 rescore if ambiguous, gather.
// ---------------------------------------------------------------------------
__global__ __launch_bounds__(256)
void finalize_kernel(const float* __restrict__ x,
                     const float* __restrict__ cb,
                     float* __restrict__ out) {
    const int row = blockIdx.x;
    const int tid = threadIdx.x;

    __shared__ float s_red[8];
    __shared__ float s_bcast;
    __shared__ int   s_list[RCAP];
    __shared__ int   s_n;
    __shared__ int   s_ovf;
    __shared__ int   s_best;

    if (tid == 0) { s_n = 0; s_ovf = 0; }
    __syncthreads();

    // warp 0: each lane owns one n-tile's candidate slab
    float gmax = -CUDART_INF_F;
    int cnt = 0;
    if (tid < 32) {
        cnt = g_ccnt[(size_t)row * NTILE + tid];
        if (cnt > CAP) { atomicExch(&s_ovf, 1); cnt = CAP; }
        const uint2* c = &g_cand[((size_t)row * NTILE + tid) * CAP];
        for (int p = 0; p < cnt; ++p)
            gmax = fmaxf(gmax, __uint_as_float(c[p].x));
#pragma unroll
        for (int o = 16; o; o >>= 1) gmax = fmaxf(gmax, __shfl_xor_sync(~0u, gmax, o));
        if (tid == 0) s_bcast = gmax;
    }
    __syncthreads();
    const float thr = s_bcast - MARGIN;
    if (tid < 32) {
        const uint2* c = &g_cand[((size_t)row * NTILE + tid) * CAP];
        for (int p = 0; p < cnt; ++p) {
            if (__uint_as_float(c[p].x) > thr) {
                int q = atomicAdd(&s_n, 1);
                if (q < RCAP) s_list[q] = (int)c[p].y;
            }
        }
    }
    __syncthreads();
    const bool full = s_ovf || (s_n > RCAP);
    const int ncand = s_n;

    if (!full && ncand == 1) {
        if (tid == 0) s_best = s_list[0];
        __syncthreads();
    } else {
        // exact fp32 rescore: candidates (or all codes on overflow)
        const int ntot = full ? N_CODES : ncand;
        float bv = -CUDART_INF_F;
        int best = N_CODES;
        const float4 a = ((const float4*)(x + (size_t)row * K_DIM))[tid];
        for (int ci = 0; ci < ntot; ++ci) {
            const int code = full ? ci : s_list[ci];
            const float4 b = ((const float4*)(cb + (size_t)code * K_DIM))[tid];
            float p = a.x * b.x + a.y * b.y + a.z * b.z + a.w * b.w;
#pragma unroll
            for (int o = 16; o; o >>= 1) p += __shfl_xor_sync(~0u, p, o);
            if ((tid & 31) == 0) s_red[tid >> 5] = p;
            __syncthreads();
            if (tid == 0) {
                float s = 0.f;
#pragma unroll
                for (int j = 0; j < 8; ++j) s += s_red[j];
                s_bcast = s;
            }
            __syncthreads();
            const float dot = s_bcast;
            if (dot > bv || (dot == bv && code < best)) { bv = dot; best = code; }
            __syncthreads();
        }
        if (tid == 0) s_best = best;
        __syncthreads();
    }

    const float4* src = (const float4*)(cb + (size_t)s_best * K_DIM);
    float4* dst = (float4*)(out + (size_t)row * K_DIM);
    dst[tid] = src[tid];
}

// ---------------------------------------------------------------------------
extern "C" void kernel_launch(void* const* d_in, const int* in_sizes, int n_in,
                              void* d_out, int out_size) {
    const float* x  = (const float*)d_in[0];   // [8,2048,1024]
    const float* cb = (const float*)d_in[1];   // [8192,1024]
    float* out = (float*)d_out;

    const int smem = STAGES * (BM + BN) * 128; // 147456
    cudaFuncSetAttribute(gemm_f16_kernel,
                         cudaFuncAttributeMaxDynamicSharedMemorySize, smem);

    cvt_x_kernel<<<(M_TOTAL * K_DIM / 8 + 255) / 256, 256>>>(x);
    cvt_cb_kernel<<<(N_CODES * K_DIM / 8 + 255) / 256, 256>>>(cb);

    dim3 grid(N_CODES / BN, M_TOTAL / BM);     // (32, 128)
    gemm_f16_kernel<<<grid, 512, smem>>>();

    finalize_kernel<<<M_TOTAL, 256>>>(x, cb, out);
}